// round 2
// baseline (speedup 1.0000x reference)
#include <cuda_runtime.h>
#include <cstddef>

// HealEncoding: out[b, f*NLVL + l] = sum_{n<4} params[l, neigh_pix[l,n,b], f] * neigh_weight[l,n,b]
//   (reference does transpose(reps,(1,2,0)).reshape -> feature-major, level-minor columns)
// params:       (8, 196608, 8) fp32
// neigh_pix:    (8, 4, 1000000) int32
// neigh_weight: (8, 4, 1000000) fp32
// out:          (1000000, 64) fp32

#define NLVL  8
#define FDIM  8
#define NPIX  196608
#define BATCH 1000000

// Block: 32 (batch lane) x 8 (level). Warp == one level for 32 consecutive b.
// - index/weight loads: fully coalesced (128B per warp LDG)
// - gathers: 32B (2x float4) fully used per thread, hot tables live in L1/L2
// - output: staged through padded shared tile -> 128B coalesced stores
__global__ void __launch_bounds__(256, 8)
heal_encoding_kernel(const float* __restrict__ params,
                     const int*   __restrict__ neigh_pix,
                     const float* __restrict__ neigh_weight,
                     float*       __restrict__ out)
{
    __shared__ float s[64 * 33];   // [out-column 0..63][b_local 0..31], stride 33 -> conflict-free

    const int lane = threadIdx.x;          // b offset within tile
    const int lvl  = threadIdx.y;          // level (one warp per level)
    const int b    = blockIdx.x * 32 + lane;

    const float4* __restrict__ p4 =
        reinterpret_cast<const float4*>(params) + (size_t)lvl * (NPIX * 2);

    // Batch the 4 index + 4 weight loads (coalesced), then 8 independent float4
    // gathers -> high MLP before the FMA chain.
    int   pix[4];
    float w[4];
#pragma unroll
    for (int n = 0; n < 4; n++) {
        const size_t off = (size_t)(lvl * 4 + n) * BATCH + b;
        pix[n] = __ldg(&neigh_pix[off]);
        w[n]   = __ldg(&neigh_weight[off]);
    }

    float4 lo[4], hi[4];
#pragma unroll
    for (int n = 0; n < 4; n++) {
        const size_t r = (size_t)pix[n] * 2;
        lo[n] = __ldg(&p4[r]);
        hi[n] = __ldg(&p4[r + 1]);
    }

    float4 a0 = make_float4(0.f, 0.f, 0.f, 0.f);
    float4 a1 = make_float4(0.f, 0.f, 0.f, 0.f);
#pragma unroll
    for (int n = 0; n < 4; n++) {
        a0.x = fmaf(w[n], lo[n].x, a0.x);
        a0.y = fmaf(w[n], lo[n].y, a0.y);
        a0.z = fmaf(w[n], lo[n].z, a0.z);
        a0.w = fmaf(w[n], lo[n].w, a0.w);
        a1.x = fmaf(w[n], hi[n].x, a1.x);
        a1.y = fmaf(w[n], hi[n].y, a1.y);
        a1.z = fmaf(w[n], hi[n].z, a1.z);
        a1.w = fmaf(w[n], hi[n].w, a1.w);
    }

    // Stage: out column for (f, lvl) is c = f*8 + lvl (feature-major, level-minor).
    // Fixed row per store, lanes span distinct b_local -> conflict-free.
    s[(0 * NLVL + lvl) * 33 + lane] = a0.x;   // f=0
    s[(1 * NLVL + lvl) * 33 + lane] = a0.y;   // f=1
    s[(2 * NLVL + lvl) * 33 + lane] = a0.z;   // f=2
    s[(3 * NLVL + lvl) * 33 + lane] = a0.w;   // f=3
    s[(4 * NLVL + lvl) * 33 + lane] = a1.x;   // f=4
    s[(5 * NLVL + lvl) * 33 + lane] = a1.y;   // f=5
    s[(6 * NLVL + lvl) * 33 + lane] = a1.z;   // f=6
    s[(7 * NLVL + lvl) * 33 + lane] = a1.w;   // f=7

    __syncthreads();

    // Coalesced write-out of the 32x64 tile (2048 floats, 256 threads, 8 iters).
    // Within a warp: consecutive c -> bank (c*33 + bl) % 32 all distinct.
    const int tid = threadIdx.y * 32 + threadIdx.x;
    float* __restrict__ outp = out + (size_t)blockIdx.x * 32 * 64;
#pragma unroll
    for (int i = 0; i < 8; i++) {
        const int e  = tid + i * 256;
        const int bl = e >> 6;
        const int c  = e & 63;
        outp[e] = s[c * 33 + bl];
    }
}

extern "C" void kernel_launch(void* const* d_in, const int* in_sizes, int n_in,
                              void* d_out, int out_size)
{
    const float* params       = (const float*)d_in[0];
    const int*   neigh_pix    = (const int*)d_in[1];
    const float* neigh_weight = (const float*)d_in[2];
    float*       out          = (float*)d_out;

    dim3 block(32, 8);
    dim3 grid(BATCH / 32);   // 1,000,000 / 32 = 31,250
    heal_encoding_kernel<<<grid, block>>>(params, neigh_pix, neigh_weight, out);
}

// round 3
// speedup vs baseline: 1.3928x; 1.3928x over previous
#include <cuda_runtime.h>
#include <cstddef>

// HealEncoding: out[b, f*NLVL + l] = sum_{n<4} params[l, neigh_pix[l,n,b], f] * neigh_weight[l,n,b]
// params:       (8, 196608, 8) fp32
// neigh_pix:    (8, 4, 1000000) int32
// neigh_weight: (8, 4, 1000000) fp32
// out:          (1000000, 64) fp32

#define NLVL  8
#define FDIM  8
#define NPIX  196608
#define BATCH 1000000
#define BBLK  16          // batch elements per block

// Block (32, 8): warp = one level. PAIR-COOPERATIVE gather: lanes 2j,2j+1 split
// the 32B feature row of batch element j's pixel (h = lane&1 picks the 16B half),
// so each warp-level LDG.128 covers 16 pixels with intra-line pair coalescing:
// 1 L1 wavefront per pixel instead of 2 (old lo/hi split = 2 instrs on the same
// line). Halves L1tex wavefront traffic, which ncu showed as the 92% bottleneck.
__global__ void __launch_bounds__(256, 8)
heal_encoding_kernel(const float* __restrict__ params,
                     const int*   __restrict__ neigh_pix,
                     const float* __restrict__ neigh_weight,
                     float*       __restrict__ out)
{
    // Staging tile: 64 out-columns x 16 b, swizzled idx = c*16 + (c>>1) + j.
    // Store banks: 16*(lvl&1) + 16*h + 4*k + (lvl>>1) + j  -> h-halves disjoint,
    // j in [0,16) -> conflict-free. Readout over 32 consecutive c also hits all
    // 32 banks (16*(c&1) + (c>>1) alternation). Conflict-free both ways.
    __shared__ float s[64 * 16 + 32];

    const int lane = threadIdx.x;
    const int lvl  = threadIdx.y;          // warp == level
    const int j    = lane >> 1;            // batch element within tile [0,16)
    const int h    = lane & 1;             // which 16B half of the 32B feature row
    const int b    = blockIdx.x * BBLK + j;

    const float4* __restrict__ p4 =
        reinterpret_cast<const float4*>(params) + (size_t)lvl * (NPIX * 2);

    // Index/weight loads: pair lanes load the same address (HW broadcast),
    // warp touches one 64B run -> 1 wavefront each.
    int   pix[4];
    float w[4];
#pragma unroll
    for (int n = 0; n < 4; n++) {
        const size_t off = (size_t)(lvl * 4 + n) * BATCH + b;
        pix[n] = __ldg(&neigh_pix[off]);
        w[n]   = __ldg(&neigh_weight[off]);
    }

    // 4 gathers, each a single LDG.128 per warp covering 16 pixels.
    float4 g[4];
#pragma unroll
    for (int n = 0; n < 4; n++) {
        g[n] = __ldg(&p4[(size_t)pix[n] * 2 + h]);
    }

    float4 a = make_float4(0.f, 0.f, 0.f, 0.f);
#pragma unroll
    for (int n = 0; n < 4; n++) {
        a.x = fmaf(w[n], g[n].x, a.x);
        a.y = fmaf(w[n], g[n].y, a.y);
        a.z = fmaf(w[n], g[n].z, a.z);
        a.w = fmaf(w[n], g[n].w, a.w);
    }

    // This thread owns features f = 4h..4h+3; out column c = f*8 + lvl.
#pragma unroll
    for (int k = 0; k < 4; k++) {
        const int c = (h * 4 + k) * NLVL + lvl;
        const float v = (k == 0) ? a.x : (k == 1) ? a.y : (k == 2) ? a.z : a.w;
        s[c * 16 + (c >> 1) + j] = v;
    }

    __syncthreads();

    // Coalesced write-out: 16 b x 64 cols = 1024 floats, 256 threads, 4 iters.
    const int tid = threadIdx.y * 32 + threadIdx.x;
    float* __restrict__ outp = out + (size_t)blockIdx.x * BBLK * 64;
#pragma unroll
    for (int i = 0; i < 4; i++) {
        const int e  = i * 256 + tid;
        const int bl = e >> 6;
        const int c  = e & 63;
        outp[e] = s[c * 16 + (c >> 1) + bl];
    }
}

extern "C" void kernel_launch(void* const* d_in, const int* in_sizes, int n_in,
                              void* d_out, int out_size)
{
    const float* params       = (const float*)d_in[0];
    const int*   neigh_pix    = (const int*)d_in[1];
    const float* neigh_weight = (const float*)d_in[2];
    float*       out          = (float*)d_out;

    dim3 block(32, 8);
    dim3 grid(BATCH / BBLK);   // 62,500
    heal_encoding_kernel<<<grid, block>>>(params, neigh_pix, neigh_weight, out);
}